// round 16
// baseline (speedup 1.0000x reference)
#include <cuda_runtime.h>
#include <cuda_fp16.h>
#include <math.h>
#include <float.h>
#include <stdint.h>

#define B_   8
#define V_   4
#define N_   16384
#define CP_  256
#define BV_  (B_*V_)            // 32
#define TM_  128                // points per tile
#define NT_  (N_*BV_/TM_)       // 4096 tiles
#define GRIDP 148               // persistent grid
#define A_STR 528               // padded row stride bytes (256 fp16 + 16 pad)
#define A_IMG    67584          // 128*528
#define OFF_RB   67584          // resident weights after A buffer
#define RB_BYTES 135168         // 256*528
#define DYN_SMEM (OFF_RB + RB_BYTES)   // 202752

// ---------------- device scratch (static; no allocations) -------------------
__device__ float d_stat1[14];
__device__ float d_part[BV_*8*10];   // per-slice partials: s0 s1 s2 cnt mx0..2 mn0..2
__device__ __align__(16) float d_gmax[BV_*CP_];
__device__ __align__(16) float d_gpart[BV_*CP_];
__device__ float d_mw[BV_*N_];
__device__ float d_denom[BV_];
__device__ __align__(16) unsigned char d_localA[(size_t)NT_*A_IMG];   // 277MB
__device__ __align__(16) uint32_t d_z[(size_t)BV_*N_*128];            // 268MB
__device__ __align__(16) unsigned char d_W2f[CP_*CP_*2];  // fp16 [n][k]
__device__ __align__(16) unsigned char d_W3f[CP_*CP_*2];  // fp16 [n][k] (W3 top)

// ---------------- helpers ---------------------------------------------------
__device__ __forceinline__ uint32_t sm2u(const void* p) {
    uint32_t a;
    asm("{ .reg .u64 t; cvta.to.shared.u64 t, %1; cvt.u32.u64 %0, t; }"
        : "=r"(a) : "l"(p));
    return a;
}
#define LDSM4(r, addr) \
    asm volatile("ldmatrix.sync.aligned.m8n8.x4.shared.b16 {%0,%1,%2,%3}, [%4];" \
        : "=r"((r)[0]), "=r"((r)[1]), "=r"((r)[2]), "=r"((r)[3]) : "r"(addr))
#define MMAOP(d, a, b0, b1) \
    asm volatile("mma.sync.aligned.m16n8k16.row.col.f32.f16.f16.f32 " \
        "{%0,%1,%2,%3}, {%4,%5,%6,%7}, {%8,%9}, {%0,%1,%2,%3};" \
        : "+f"((d)[0]), "+f"((d)[1]), "+f"((d)[2]), "+f"((d)[3]) \
        : "r"((a)[0]), "r"((a)[1]), "r"((a)[2]), "r"((a)[3]), "r"(b0), "r"(b1))
#define CPA16(dst, src) \
    asm volatile("cp.async.cg.shared.global [%0], [%1], 16;" :: "r"(dst), "l"(src))
#define CPCOMMIT() asm volatile("cp.async.commit_group;" ::: "memory")
#define CPWAIT0()  asm volatile("cp.async.wait_group 0;" ::: "memory")
#define CPWAITN(n) asm volatile("cp.async.wait_group %0;" :: "n"(n) : "memory")

static __device__ __forceinline__ uint32_t pack2h(float v0, float v1) {
    __half h0 = __float2half_rn(v0);
    __half h1 = __float2half_rn(v1);
    return (uint32_t)__half_as_ushort(h0) | ((uint32_t)__half_as_ushort(h1) << 16);
}
__device__ __forceinline__ void atomicMaxFloat(float* addr, float val) {
    if (__float_as_int(val) >= 0) atomicMax((int*)addr, __float_as_int(val));
    else atomicMin((unsigned int*)addr, __float_as_uint(val));
}

__device__ __forceinline__ void loadResidentB(uint32_t su, const unsigned char* g, int tid) {
    for (int i = tid; i < 8192; i += 256) {
        int row = i >> 5, q = i & 31;
        CPA16(su + OFF_RB + (uint32_t)row*A_STR + q*16, g + (size_t)i*16);
    }
}

// K=256 mainloop, M=128: 4 m-strips per warp, B resident, zero syncs (kG1)
#define MAINLOOP_R(ab) \
    _Pragma("unroll 1") \
    for (int ch = 0; ch < 8; ch++) { \
        _Pragma("unroll") \
        for (int kb = 0; kb < 2; kb++) { \
            uint32_t kA = (uint32_t)(ch*64 + kb*32); \
            uint32_t a0[4], a1[4], a2[4], a3[4]; \
            LDSM4(a0, (ab) + aoff0 + kA); \
            LDSM4(a1, (ab) + aoff0 + 16896u + kA); \
            LDSM4(a2, (ab) + aoff0 + 33792u + kA); \
            LDSM4(a3, (ab) + aoff0 + 50688u + kA); \
            _Pragma("unroll") \
            for (int nt = 0; nt < 4; nt++) { \
                uint32_t bh[4]; \
                LDSM4(bh, su + OFF_RB + boff + (uint32_t)(nt*16*A_STR) + kA); \
                MMAOP(dS[0][2*nt],   a0, bh[0], bh[1]); \
                MMAOP(dS[0][2*nt+1], a0, bh[2], bh[3]); \
                MMAOP(dS[1][2*nt],   a1, bh[0], bh[1]); \
                MMAOP(dS[1][2*nt+1], a1, bh[2], bh[3]); \
                MMAOP(dS[2][2*nt],   a2, bh[0], bh[1]); \
                MMAOP(dS[2][2*nt+1], a2, bh[2], bh[3]); \
                MMAOP(dS[3][2*nt],   a3, bh[0], bh[1]); \
                MMAOP(dS[3][2*nt+1], a3, bh[2], bh[3]); \
            } \
        } \
    }

// one K64 chunk of compute (kG2 pipelined path)
#define COMPUTE_CH(ch) \
    { \
        _Pragma("unroll") \
        for (int kb = 0; kb < 2; kb++) { \
            uint32_t kA = (uint32_t)((ch)*64 + kb*32); \
            uint32_t a0[4], a1[4], a2[4], a3[4]; \
            LDSM4(a0, su + aoff0 + kA); \
            LDSM4(a1, su + aoff0 + 16896u + kA); \
            LDSM4(a2, su + aoff0 + 33792u + kA); \
            LDSM4(a3, su + aoff0 + 50688u + kA); \
            _Pragma("unroll") \
            for (int nt = 0; nt < 4; nt++) { \
                uint32_t bh[4]; \
                LDSM4(bh, su + OFF_RB + boff + (uint32_t)(nt*16*A_STR) + kA); \
                MMAOP(dS[0][2*nt],   a0, bh[0], bh[1]); \
                MMAOP(dS[0][2*nt+1], a0, bh[2], bh[3]); \
                MMAOP(dS[1][2*nt],   a1, bh[0], bh[1]); \
                MMAOP(dS[1][2*nt+1], a1, bh[2], bh[3]); \
                MMAOP(dS[2][2*nt],   a2, bh[0], bh[1]); \
                MMAOP(dS[2][2*nt+1], a2, bh[2], bh[3]); \
                MMAOP(dS[3][2*nt],   a3, bh[0], bh[1]); \
                MMAOP(dS[3][2*nt+1], a3, bh[2], bh[3]); \
            } \
        } \
    }

#define STAGE(j) CPWAITN(7-(j)); __syncthreads(); COMPUTE_CH(j)

// issue tile's A as 8 chunk groups (64B-per-row strided slices)
__device__ __forceinline__ void issueAChunks(uint32_t su, const unsigned char* lw, int tid) {
    #pragma unroll
    for (int ch = 0; ch < 8; ch++) {
        #pragma unroll
        for (int i = 0; i < 2; i++) {
            int w = tid + i*256;          // 0..511
            int row = w >> 2, q = w & 3;
            uint32_t off = (uint32_t)row*A_STR + (uint32_t)ch*64 + q*16;
            CPA16(su + off, lw + off);
        }
        CPCOMMIT();
    }
}

// ---------------- kPre: fused preprocessing ---------------------------------
__global__ void __launch_bounds__(256) kPre(const float* __restrict__ W2,
    const float* __restrict__ W3, const float* __restrict__ W1,
    const float* __restrict__ b1, const float* __restrict__ xyz,
    const float* __restrict__ masks)
{
    int blk = blockIdx.x;
    int tid = threadIdx.x;

    if (blk < 256) {
        int k = blk, n = tid;
        size_t pos = ((size_t)n*CP_ + k)*2;
        *(unsigned short*)(d_W2f + pos) = __half_as_ushort(__float2half_rn(W2[k*CP_ + n]));
        *(unsigned short*)(d_W3f + pos) = __half_as_ushort(__float2half_rn(W3[k*CP_ + n]));
        return;
    }
    if (blk == 256) {
        __shared__ float sm[14][256];
        int c = tid;
        float b = b1[c], w0 = W1[c], w1 = W1[CP_+c], w2 = W1[2*CP_+c];
        sm[0][c]=b;      sm[1][c]=b*b;
        sm[2][c]=w0;     sm[3][c]=w1;     sm[4][c]=w2;
        sm[5][c]=b*w0;   sm[6][c]=b*w1;   sm[7][c]=b*w2;
        sm[8][c]=w0*w0;  sm[9][c]=w0*w1;  sm[10][c]=w0*w2;
        sm[11][c]=w1*w1; sm[12][c]=w1*w2; sm[13][c]=w2*w2;
        __syncthreads();
        for (int s = 128; s > 0; s >>= 1) {
            if (c < s) {
                #pragma unroll
                for (int q = 0; q < 14; q++) sm[q][c] += sm[q][c+s];
            }
            __syncthreads();
        }
        if (c < 14) d_stat1[c] = sm[c][0];
        return;
    }
    if (blk == 257) {
        for (int i = tid; i < BV_*CP_; i += 256) d_gmax[i] = -FLT_MAX;
        if (tid < BV_) d_denom[tid] = 0.f;
        return;
    }

    int blk2 = blk - 258;
    int bv = blk2 >> 3, slice = blk2 & 7;
    int b  = bv >> 2;
    int n0 = slice * (N_/8);

    float s0=0.f, s1=0.f, s2=0.f, cnt=0.f;
    float mx0=-FLT_MAX, mx1=-FLT_MAX, mx2=-FLT_MAX;
    float mn0= FLT_MAX, mn1= FLT_MAX, mn2= FLT_MAX;
    const float* mrow = masks + (size_t)bv*N_ + n0;
    const float* x0r  = xyz + (size_t)(b*3+0)*N_ + n0;
    const float* x1r  = xyz + (size_t)(b*3+1)*N_ + n0;
    const float* x2r  = xyz + (size_t)(b*3+2)*N_ + n0;
    for (int n = tid; n < N_/8; n += 256) {
        float m = mrow[n];
        float a = x0r[n]*m, c = x1r[n]*m, e = x2r[n]*m;
        s0 += a; s1 += c; s2 += e; cnt += m;
        mx0 = fmaxf(mx0,a); mx1 = fmaxf(mx1,c); mx2 = fmaxf(mx2,e);
        mn0 = fminf(mn0,a); mn1 = fminf(mn1,c); mn2 = fminf(mn2,e);
    }
    __shared__ float rs[10][256];
    rs[0][tid]=s0; rs[1][tid]=s1; rs[2][tid]=s2; rs[3][tid]=cnt;
    rs[4][tid]=mx0; rs[5][tid]=mx1; rs[6][tid]=mx2;
    rs[7][tid]=mn0; rs[8][tid]=mn1; rs[9][tid]=mn2;
    __syncthreads();
    for (int s = 128; s > 0; s >>= 1) {
        if (tid < s) {
            #pragma unroll
            for (int q = 0; q < 4; q++) rs[q][tid] += rs[q][tid+s];
            #pragma unroll
            for (int q = 4; q < 7; q++) rs[q][tid] = fmaxf(rs[q][tid], rs[q][tid+s]);
            #pragma unroll
            for (int q = 7; q < 10; q++) rs[q][tid] = fminf(rs[q][tid], rs[q][tid+s]);
        }
        __syncthreads();
    }
    if (tid < 10) d_part[(size_t)blk2*10 + tid] = rs[tid][0];
}

// ---- kG1 (persistent, M=128): stage1 -> GEMM(W2) -> reg-LN2 -> local+gmax --
__global__ void __launch_bounds__(256) kG1(const float* __restrict__ xyz,
    const float* __restrict__ W1, const float* __restrict__ b1,
    const float* __restrict__ g1, const float* __restrict__ be1,
    const float* __restrict__ b2, const float* __restrict__ g2,
    const float* __restrict__ be2)
{
    extern __shared__ unsigned char ds[];
    __shared__ float w1s[3*CP_];
    __shared__ float b1s[CP_], g1s[CP_], e1s[CP_], b2s[CP_], g2s[CP_], e2s[CP_];
    __shared__ float srS[TM_][4], srQ[TM_][4];
    __shared__ float sMean[TM_], sRstd[TM_];
    __shared__ float scx[2][CP_];
    __shared__ float sCen[3*BV_], sInv[BV_], sSt[14];

    int tid = threadIdx.x, lane = tid & 31, wid = tid >> 5;
    uint32_t su = sm2u(ds);

    loadResidentB(su, d_W2f, tid); CPCOMMIT();

    for (int i = tid; i < 3*CP_; i += 256) w1s[i] = W1[i];
    b1s[tid]=b1[tid]; g1s[tid]=g1[tid]; e1s[tid]=be1[tid];
    b2s[tid]=b2[tid]; g2s[tid]=g2[tid]; e2s[tid]=be2[tid];
    if (tid < BV_) {
        float s0=0.f,s1=0.f,s2=0.f,cnt=0.f;
        float mx0=-FLT_MAX,mx1=-FLT_MAX,mx2=-FLT_MAX;
        float mn0=FLT_MAX,mn1=FLT_MAX,mn2=FLT_MAX;
        #pragma unroll
        for (int sl = 0; sl < 8; sl++) {
            const float* pp = d_part + (size_t)(tid*8+sl)*10;
            s0+=pp[0]; s1+=pp[1]; s2+=pp[2]; cnt+=pp[3];
            mx0=fmaxf(mx0,pp[4]); mx1=fmaxf(mx1,pp[5]); mx2=fmaxf(mx2,pp[6]);
            mn0=fminf(mn0,pp[7]); mn1=fminf(mn1,pp[8]); mn2=fminf(mn2,pp[9]);
        }
        float valid = fmaxf(cnt, 1.f);
        sCen[tid*3+0]=s0/valid; sCen[tid*3+1]=s1/valid; sCen[tid*3+2]=s2/valid;
        float diam = fmaxf(fmaxf(mx0-mn0, mx1-mn1), mx2-mn2);
        if (diam == 0.f) diam = 1.f;
        sInv[tid] = 1.f/diam;
    }
    if (tid < 14) sSt[tid] = d_stat1[tid];
    CPWAIT0();
    __syncthreads();

    int p = tid >> 1, half = tid & 1, c0 = half*128;
    int mt0 = (wid >> 2) * 16;
    int nb  = (wid & 3) * 64;
    uint32_t aoff0 = (uint32_t)(mt0 + (lane&7) + ((lane>>3)&1)*8)*A_STR + (lane>>4)*16;
    uint32_t boff  = (uint32_t)(nb + (lane&7) + (lane>>4)*8)*A_STR + ((lane>>3)&1)*16;
    int r = lane >> 2, q2 = (lane & 3)*2;

    for (int tile = blockIdx.x; tile < NT_; tile += GRIDP) {
        int bv = tile >> 7;
        int b  = bv >> 2;

        int n = (tile & 127) * TM_ + p;
        float idm = sInv[bv];
        float x0 = (xyz[(size_t)(b*3+0)*N_ + n] - sCen[bv*3+0]) * idm;
        float x1 = (xyz[(size_t)(b*3+1)*N_ + n] - sCen[bv*3+1]) * idm;
        float x2 = (xyz[(size_t)(b*3+2)*N_ + n] - sCen[bv*3+2]) * idm;
        float S  = sSt[0] + x0*sSt[2] + x1*sSt[3] + x2*sSt[4];
        float E2 = sSt[1] + 2.f*(x0*sSt[5] + x1*sSt[6] + x2*sSt[7])
                 + x0*x0*sSt[8]  + 2.f*x0*x1*sSt[9] + 2.f*x0*x2*sSt[10]
                 + x1*x1*sSt[11] + 2.f*x1*x2*sSt[12] + x2*x2*sSt[13];
        float mean = S * (1.f/CP_);
        float rstd = rsqrtf(E2*(1.f/CP_) - mean*mean + 1e-5f);
        #pragma unroll 8
        for (int i = 0; i < 64; i++) {
            int c = c0 + 2*i;
            float y0 = b1s[c]   + x0*w1s[c]   + x1*w1s[CP_+c]   + x2*w1s[2*CP_+c];
            float y1 = b1s[c+1] + x0*w1s[c+1] + x1*w1s[CP_+c+1] + x2*w1s[2*CP_+c+1];
            y0 = fmaxf((y0-mean)*rstd*g1s[c]   + e1s[c],   0.f);
            y1 = fmaxf((y1-mean)*rstd*g1s[c+1] + e1s[c+1], 0.f);
            *(uint32_t*)(ds + (size_t)p*A_STR + c*2) = pack2h(y0, y1);
        }
        __syncthreads();

        float dS[4][8][4] = {};
        MAINLOOP_R(su)

        float rsm[4][2] = {}, rqm[4][2] = {};
        #pragma unroll
        for (int s = 0; s < 4; s++) {
            #pragma unroll
            for (int f = 0; f < 8; f++) {
                int c = nb + f*8 + q2;
                float bb0 = b2s[c], bb1 = b2s[c+1], v;
                v = dS[s][f][0]+bb0; rsm[s][0]+=v; rqm[s][0]+=v*v;
                v = dS[s][f][1]+bb1; rsm[s][0]+=v; rqm[s][0]+=v*v;
                v = dS[s][f][2]+bb0; rsm[s][1]+=v; rqm[s][1]+=v*v;
                v = dS[s][f][3]+bb1; rsm[s][1]+=v; rqm[s][1]+=v*v;
            }
        }
        #pragma unroll
        for (int s = 0; s < 4; s++) {
            #pragma unroll
            for (int h = 0; h < 2; h++) {
                rsm[s][h] += __shfl_xor_sync(~0u, rsm[s][h], 1);
                rsm[s][h] += __shfl_xor_sync(~0u, rsm[s][h], 2);
                rqm[s][h] += __shfl_xor_sync(~0u, rqm[s][h], 1);
                rqm[s][h] += __shfl_xor_sync(~0u, rqm[s][h], 2);
            }
        }
        if ((lane & 3) == 0) {
            int w4 = wid & 3;
            #pragma unroll
            for (int s = 0; s < 4; s++) {
                #pragma unroll
                for (int h = 0; h < 2; h++) {
                    int row = mt0 + s*32 + h*8 + r;
                    srS[row][w4] = rsm[s][h];
                    srQ[row][w4] = rqm[s][h];
                }
            }
        }
        __syncthreads();
        if (tid < TM_) {
            float Ss = srS[tid][0]+srS[tid][1]+srS[tid][2]+srS[tid][3];
            float Qs = srQ[tid][0]+srQ[tid][1]+srQ[tid][2]+srQ[tid][3];
            float mn = Ss * (1.f/CP_);
            sMean[tid] = mn;
            sRstd[tid] = rsqrtf(Qs*(1.f/CP_) - mn*mn + 1e-5f);
        }
        __syncthreads();

        {
            unsigned char* lw = d_localA + (size_t)tile*A_IMG;
            float cm[16];
            #pragma unroll
            for (int i = 0; i < 16; i++) cm[i] = -FLT_MAX;
            #pragma unroll
            for (int s = 0; s < 4; s++) {
                int row0 = mt0 + s*32 + r, row1 = row0 + 8;
                float m0 = sMean[row0], rr0 = sRstd[row0];
                float m1 = sMean[row1], rr1 = sRstd[row1];
                #pragma unroll
                for (int f = 0; f < 8; f++) {
                    int c = nb + f*8 + q2;
                    float bb0=b2s[c], bb1=b2s[c+1], g0=g2s[c], g1=g2s[c+1];
                    float e0=e2s[c], e1=e2s[c+1];
                    float v00 = (dS[s][f][0]+bb0-m0)*rr0*g0+e0;
                    float v01 = (dS[s][f][1]+bb1-m0)*rr0*g1+e1;
                    float v10 = (dS[s][f][2]+bb0-m1)*rr1*g0+e0;
                    float v11 = (dS[s][f][3]+bb1-m1)*rr1*g1+e1;
                    *(uint32_t*)(lw + (size_t)row0*A_STR + c*2) = pack2h(v00, v01);
                    *(uint32_t*)(lw + (size_t)row1*A_STR + c*2) = pack2h(v10, v11);
                    cm[2*f]   = fmaxf(cm[2*f],   fmaxf(v00, v10));
                    cm[2*f+1] = fmaxf(cm[2*f+1], fmaxf(v01, v11));
                }
            }
            #pragma unroll
            for (int i = 0; i < 16; i++) {
                cm[i] = fmaxf(cm[i], __shfl_xor_sync(~0u, cm[i], 4));
                cm[i] = fmaxf(cm[i], __shfl_xor_sync(~0u, cm[i], 8));
                cm[i] = fmaxf(cm[i], __shfl_xor_sync(~0u, cm[i], 16));
            }
            if ((lane >> 2) == 0) {
                int grp = wid >> 2;
                #pragma unroll
                for (int f = 0; f < 8; f++) {
                    int c = nb + f*8 + q2;
                    scx[grp][c]   = cm[2*f];
                    scx[grp][c+1] = cm[2*f+1];
                }
            }
        }
        __syncthreads();
        atomicMaxFloat(&d_gmax[bv*CP_ + tid], fmaxf(scx[0][tid], scx[1][tid]));
        __syncthreads();
    }
}

// ---- kG2 (persistent, M=128): K-chunk-pipelined A load, W3 resident --------
__global__ void __launch_bounds__(256) kG2() {
    extern __shared__ unsigned char ds[];
    int tid = threadIdx.x, lane = tid & 31, wid = tid >> 5;
    uint32_t su = sm2u(ds);

    loadResidentB(su, d_W3f, tid); CPCOMMIT();
    if (blockIdx.x < NT_)
        issueAChunks(su, d_localA + (size_t)blockIdx.x*A_IMG, tid);

    int mt0 = (wid >> 2) * 16;
    int nb  = (wid & 3) * 64;
    uint32_t aoff0 = (uint32_t)(mt0 + (lane&7) + ((lane>>3)&1)*8)*A_STR + (lane>>4)*16;
    uint32_t boff  = (uint32_t)(nb + (lane&7) + (lane>>4)*8)*A_STR + ((lane>>3)&1)*16;
    int r = lane >> 2, q2 = (lane & 3)*2;

    for (int tile = blockIdx.x; tile < NT_; tile += GRIDP) {
        float dS[4][8][4] = {};
        STAGE(0); STAGE(1); STAGE(2); STAGE(3);
        STAGE(4); STAGE(5); STAGE(6); STAGE(7);
        __syncthreads();   // all ldsm reads complete before buffer refill

        {   // issue next tile's chunks; z-store epilogue overlaps them
            int nxt = tile + GRIDP;
            if (nxt < NT_)
                issueAChunks(su, d_localA + (size_t)nxt*A_IMG, tid);
        }

        uint32_t* zb = d_z + (size_t)tile*TM_*128;
        #pragma unroll
        for (int s = 0; s < 4; s++) {
            int row0 = mt0 + s*32 + r, row1 = row0 + 8;
            #pragma unroll
            for (int f = 0; f < 8; f++) {
                int cw = (nb + f*8 + q2) >> 1;
                zb[(size_t)row0*128 + cw] = pack2h(dS[s][f][0], dS[s][f][1]);
                zb[(size_t)row1*128 + cw] = pack2h(dS[s][f][2], dS[s][f][3]);
            }
        }
    }
}

// ---------------- kC: gpart = global_xyz @ W3[256:512] + b3 -----------------
__global__ void __launch_bounds__(256) kC(const float* __restrict__ W3,
                                          const float* __restrict__ b3) {
    int bv = blockIdx.x;
    int c  = threadIdx.x;
    __shared__ float sg[CP_];
    __shared__ float ws[32*CP_];
    sg[c] = d_gmax[bv*CP_ + c];
    float acc = b3[c];
    for (int ko = 0; ko < 8; ko++) {
        __syncthreads();
        const float4* src = (const float4*)(W3 + (size_t)(256 + ko*32)*CP_);
        for (int i = c; i < 32*CP_/4; i += 256) ((float4*)ws)[i] = src[i];
        __syncthreads();
        #pragma unroll 8
        for (int kk = 0; kk < 32; kk++)
            acc += sg[ko*32+kk] * ws[kk*CP_ + c];
    }
    d_gpart[bv*CP_ + c] = acc;
}

// ---------------- kD: streaming LN3 + ReLU + W4 -> weights ------------------
__global__ void __launch_bounds__(256) kD(const float* __restrict__ masks,
    const float* __restrict__ g3, const float* __restrict__ be3,
    const float* __restrict__ W4)
{
    __shared__ float sGp[CP_], sG3[CP_], sE3[CP_], sW4[CP_];
    int blk = blockIdx.x;
    int bv = blk >> 5;
    int pbase = (blk & 31) * 512;
    int tid = threadIdx.x, lane = tid & 31, wid = tid >> 5;

    sGp[tid] = d_gpart[bv*CP_ + tid];
    sG3[tid] = g3[tid]; sE3[tid] = be3[tid]; sW4[tid] = W4[tid];
    __syncthreads();

    int cbase = lane*8;
    float gp[8], gg[8], ee[8], ww[8];
    #pragma unroll
    for (int j = 0; j < 8; j++) {
        gp[j]=sGp[cbase+j]; gg[j]=sG3[cbase+j]; ee[j]=sE3[cbase+j]; ww[j]=sW4[cbase+j];
    }

    float dacc = 0.f;
    for (int pp = wid; pp < 512; pp += 8) {
        int n = pbase + pp;
        size_t pt = (size_t)bv*N_ + n;
        uint4 w = *(const uint4*)(d_z + pt*128 + lane*4);
        uint32_t ws4[4] = {w.x, w.y, w.z, w.w};
        float v[8];
        #pragma unroll
        for (int j = 0; j < 4; j++) {
            __half2 h2 = *reinterpret_cast<__half2*>(&ws4[j]);
            float2 f = __half22float2(h2);
            v[2*j]   = f.x + gp[2*j];
            v[2*j+1] = f.y + gp[2*j+1];
        }
        float s = 0.f, q = 0.f;
        #pragma unroll
        for (int j = 0; j < 8; j++) { s += v[j]; q += v[j]*v[j]; }
        #pragma unroll
        for (int o = 16; o > 0; o >>= 1) {
            s += __shfl_xor_sync(~0u, s, o);
            q += __shfl_xor_sync(~0u, q, o);
        }
        float mean = s * (1.f/CP_);
        float rstd = rsqrtf(q*(1.f/CP_) - mean*mean + 1e-5f);
        float dot = 0.f;
        #pragma unroll
        for (int j = 0; j < 8; j++)
            dot += fmaxf((v[j]-mean)*rstd*gg[j] + ee[j], 0.f) * ww[j];
        #pragma unroll
        for (int o = 16; o > 0; o >>= 1) dot += __shfl_xor_sync(~0u, dot, o);
        if (lane == 0) {
            float m = masks[pt];
            float wgt = 2.f * m / (1.f + expf(-dot));
            d_mw[pt] = wgt;
            dacc += wgt;
        }
    }
    if (lane == 0) atomicAdd(&d_denom[bv], dacc);
}

// ---------------- kE: weighted pooling + epilogue ---------------------------
__global__ void __launch_bounds__(256) kE(const float* __restrict__ feats,
                                          float* __restrict__ out) {
    int blk = blockIdx.x;
    int b = blk >> 8;
    int c = blk & 255;
    int tid = threadIdx.x;

    const float* f   = feats + (size_t)(b*CP_ + c)*N_;
    const float* mw0 = d_mw + (size_t)(b*4+0)*N_;
    const float* mw1 = d_mw + (size_t)(b*4+1)*N_;
    const float* mw2 = d_mw + (size_t)(b*4+2)*N_;
    const float* mw3 = d_mw + (size_t)(b*4+3)*N_;

    float a0=0.f, a1=0.f, a2=0.f, a3=0.f;
    for (int n = tid; n < N_; n += 256) {
        float fv = f[n];
        a0 += fv*mw0[n]; a1 += fv*mw1[n]; a2 += fv*mw2[n]; a3 += fv*mw3[n];
    }
    #pragma unroll
    for (int o = 16; o > 0; o >>= 1) {
        a0 += __shfl_xor_sync(0xffffffffu, a0, o);
        a1 += __shfl_xor_sync(0xffffffffu, a1, o);
        a2 += __shfl_xor_sync(0xffffffffu, a2, o);
        a3 += __shfl_xor_sync(0xffffffffu, a3, o);
    }
    __shared__ float sr[4][8];
    int lane = tid & 31, warp = tid >> 5;
    if (lane == 0) { sr[0][warp]=a0; sr[1][warp]=a1; sr[2][warp]=a2; sr[3][warp]=a3; }
    __syncthreads();
    if (tid < 4) {
        float ps = 0.f;
        #pragma unroll
        for (int w = 0; w < 8; w++) ps += sr[tid][w];
        int bvv = b*4 + tid;
        float den = fmaxf(d_denom[bvv], 1e-8f);
        out[(size_t)bvv*CP_ + c] = ps/den + d_gmax[bvv*CP_ + c];
    }
}

// ---------------- launch ----------------------------------------------------
extern "C" void kernel_launch(void* const* d_in, const int* in_sizes, int n_in,
                              void* d_out, int out_size) {
    const float* xyz = (const float*)d_in[0];
    const float* pf  = (const float*)d_in[1];
    const float* pm  = (const float*)d_in[2];
    const float* W1  = (const float*)d_in[3];
    const float* b1  = (const float*)d_in[4];
    const float* g1  = (const float*)d_in[5];
    const float* be1 = (const float*)d_in[6];
    const float* W2  = (const float*)d_in[7];
    const float* b2  = (const float*)d_in[8];
    const float* g2  = (const float*)d_in[9];
    const float* be2 = (const float*)d_in[10];
    const float* W3  = (const float*)d_in[11];
    const float* b3  = (const float*)d_in[12];
    const float* g3  = (const float*)d_in[13];
    const float* be3 = (const float*)d_in[14];
    const float* W4  = (const float*)d_in[15];
    float* out = (float*)d_out;

    static int configured = 0;
    if (!configured) {
        cudaFuncSetAttribute(kG1, cudaFuncAttributeMaxDynamicSharedMemorySize, DYN_SMEM);
        cudaFuncSetAttribute(kG2, cudaFuncAttributeMaxDynamicSharedMemorySize, DYN_SMEM);
        configured = 1;
    }

    kPre<<<514, 256>>>(W2, W3, W1, b1, xyz, pm);
    kG1<<<GRIDP, 256, DYN_SMEM>>>(xyz, W1, b1, g1, be1, b2, g2, be2);
    kC<<<BV_, 256>>>(W3, b3);
    kG2<<<GRIDP, 256, DYN_SMEM>>>();
    kD<<<1024, 256>>>(pm, g3, be3, W4);
    kE<<<B_*CP_, 256>>>(pf, out);
}